// round 16
// baseline (speedup 1.0000x reference)
#include <cuda_runtime.h>
#include <cuda_fp16.h>
#include <math.h>
#include <stdint.h>

// Problem constants
#define BB 8
#define NN 2048
#define FF 512
#define HH 256
#define LL 3
#define LN_EPS 1e-5f
#define NCTA 128            // layer kernel grid size (16 x 8), 1 CTA/SM

// ---------------------------------------------------------------------------
// Device scratch (static — no cudaMalloc allowed)
// ---------------------------------------------------------------------------
__device__ __align__(128) __half g_norm_adj[(size_t)BB * NN * NN];   // 67 MB
__device__ __align__(128) __half g_nf[(size_t)BB * NN * FF];         // 16.8 MB
__device__ __align__(128) float  g_h[(size_t)BB * NN * HH];          // fp32 residual
__device__ __align__(128) __half g_hTa[(size_t)BB * HH * NN];        // hT ping
__device__ __align__(128) __half g_hTb[(size_t)BB * HH * NN];        // hT pong
__device__ __align__(128) __half g_wT[256 * 512 + 3 * 256 * 256];    // W_in^T, W[l]^T

// grid barrier state (replay-safe: gen is monotonic, count self-resets)
__device__ unsigned g_bar_count[4];
__device__ unsigned g_bar_gen[4];

// ---------------------------------------------------------------------------
// Helpers
// ---------------------------------------------------------------------------
__device__ __forceinline__ uint32_t smem_u32(const void* p) {
    uint32_t a;
    asm("{ .reg .u64 t; cvta.to.shared.u64 t, %1; cvt.u32.u64 %0, t; }" : "=r"(a) : "l"(p));
    return a;
}
__device__ __forceinline__ void cp16(uint32_t dst, const void* src) {
    asm volatile("cp.async.cg.shared.global [%0], [%1], 16;" :: "r"(dst), "l"(src) : "memory");
}
__device__ __forceinline__ void cp_commit() {
    asm volatile("cp.async.commit_group;" ::: "memory");
}
template <int N> __device__ __forceinline__ void cp_wait() {
    asm volatile("cp.async.wait_group %0;" :: "n"(N) : "memory");
}
__device__ __forceinline__ void ldsm_x4(uint32_t* r, uint32_t addr) {
    asm volatile("ldmatrix.sync.aligned.m8n8.x4.shared.b16 {%0,%1,%2,%3}, [%4];"
                 : "=r"(r[0]), "=r"(r[1]), "=r"(r[2]), "=r"(r[3]) : "r"(addr));
}
__device__ __forceinline__ void ldsm_x2(uint32_t* r, uint32_t addr) {
    asm volatile("ldmatrix.sync.aligned.m8n8.x2.shared.b16 {%0,%1}, [%2];"
                 : "=r"(r[0]), "=r"(r[1]) : "r"(addr));
}
__device__ __forceinline__ void mma_f16(float* c, const uint32_t* a, const uint32_t* b) {
    asm volatile("mma.sync.aligned.m16n8k16.row.col.f32.f16.f16.f32 "
                 "{%0,%1,%2,%3}, {%4,%5,%6,%7}, {%8,%9}, {%0,%1,%2,%3};"
                 : "+f"(c[0]), "+f"(c[1]), "+f"(c[2]), "+f"(c[3])
                 : "r"(a[0]), "r"(a[1]), "r"(a[2]), "r"(a[3]), "r"(b[0]), "r"(b[1]));
}

// Device-wide barrier: all NCTA CTAs must be co-resident (they are: 1 CTA/SM).
__device__ __forceinline__ void grid_barrier(int id) {
    __syncthreads();
    if (threadIdx.x == 0) {
        __threadfence();
        unsigned gen = *(volatile unsigned*)&g_bar_gen[id];
        if (atomicAdd(&g_bar_count[id], 1u) == NCTA - 1) {
            g_bar_count[id] = 0;
            __threadfence();
            atomicAdd(&g_bar_gen[id], 1u);
        } else {
            while (*(volatile unsigned*)&g_bar_gen[id] == gen) { }
        }
    }
    __syncthreads();
}

// smem region offsets for fused kernels
#define KC 64
#define A2_OFF    147456u
#define SP_OFF    (A2_OFF + 65536u)
#define QP_OFF    (SP_OFF + 4096u)
#define MU_OFF    (QP_OFF + 4096u)
#define RS_OFF    (MU_OFF + 512u)
#define FUSED_SMEM (RS_OFF + 512u)

// ---------------------------------------------------------------------------
// Kernel 1: normalized adjacency -> fp16 (grid (NN, BB))
// ---------------------------------------------------------------------------
__global__ __launch_bounds__(256) void norm_adj_kernel(
    const float4* __restrict__ adj, const float4* __restrict__ ew,
    __half* __restrict__ out)
{
    const int row = blockIdx.x;
    const int b   = blockIdx.y;
    const long base4 = ((long)b * NN + row) * (NN / 4);
    const float4* __restrict__ arow = adj + base4;
    const float4* __restrict__ erow = ew + base4;
    __half2* __restrict__ orow = (__half2*)(out + ((long)b * NN + row) * NN);

    __shared__ float4 w4[NN / 4];
    __shared__ float sbuf[8];

    const int diag4 = row >> 2;
    const int diagc = row & 3;

    float lsum = 0.f;
#pragma unroll
    for (int i = 0; i < 2; i++) {
        int c4 = threadIdx.x + i * 256;
        float4 a = arow[c4];
        float4 e = erow[c4];
        if (c4 == diag4) {
            if (diagc == 0) a.x += 1.f;
            else if (diagc == 1) a.y += 1.f;
            else if (diagc == 2) a.z += 1.f;
            else a.w += 1.f;
        }
        float4 v;
        v.x = fminf(a.x, 1.f) * e.x;
        v.y = fminf(a.y, 1.f) * e.y;
        v.z = fminf(a.z, 1.f) * e.z;
        v.w = fminf(a.w, 1.f) * e.w;
        w4[c4] = v;
        lsum += v.x + v.y + v.z + v.w;
    }
#pragma unroll
    for (int o = 16; o > 0; o >>= 1) lsum += __shfl_down_sync(0xffffffffu, lsum, o);
    int lane = threadIdx.x & 31, wid = threadIdx.x >> 5;
    if (lane == 0) sbuf[wid] = lsum;
    __syncthreads();
    if (wid == 0) {
        float v = (lane < 8) ? sbuf[lane] : 0.f;
#pragma unroll
        for (int o = 4; o > 0; o >>= 1) v += __shfl_down_sync(0xffffffffu, v, o);
        if (lane == 0) sbuf[0] = v;
    }
    __syncthreads();
    const float inv = 1.0f / (sbuf[0] + 1e-8f);

#pragma unroll
    for (int i = 0; i < 2; i++) {
        int c4 = threadIdx.x + i * 256;
        float4 v = w4[c4];
        orow[2 * c4 + 0] = __floats2half2_rn(v.x * inv, v.y * inv);
        orow[2 * c4 + 1] = __floats2half2_rn(v.z * inv, v.w * inv);
    }
}

// ---------------------------------------------------------------------------
// Kernel 2: 32x32 transpose, fp32 -> fp16 (weights)
// ---------------------------------------------------------------------------
__global__ __launch_bounds__(256) void transpose_kernel(
    const float* __restrict__ in, __half* __restrict__ out,
    int R, int C, long sIn, long sOut)
{
    __shared__ float tile[32][33];
    const int bz = blockIdx.z;
    in  += (long)bz * sIn;
    out += (long)bz * sOut;
    const int c0 = blockIdx.x * 32;
    const int r0 = blockIdx.y * 32;
    const int tx = threadIdx.x, ty = threadIdx.y;
#pragma unroll
    for (int i = 0; i < 4; i++)
        tile[ty + i * 8][tx] = in[(long)(r0 + ty + i * 8) * C + c0 + tx];
    __syncthreads();
#pragma unroll
    for (int i = 0; i < 4; i++)
        out[(long)(c0 + ty + i * 8) * R + r0 + tx] = __float2half_rn(tile[tx][ty + i * 8]);
}

// ---------------------------------------------------------------------------
// Kernel 2b: fp32 -> fp16 copy (node_feat)
// ---------------------------------------------------------------------------
__global__ __launch_bounds__(256) void half_copy_kernel(
    const float4* __restrict__ in, __half2* __restrict__ out)
{
    long i = (long)blockIdx.x * 256 + threadIdx.x;
    float4 v = in[i];
    out[2 * i + 0] = __floats2half2_rn(v.x, v.y);
    out[2 * i + 1] = __floats2half2_rn(v.z, v.w);
}

// ---------------------------------------------------------------------------
// Kernel 3: FUSED INPUT PROJECTION (GEMM K=512 + LN epilogue), grid (128)
// ---------------------------------------------------------------------------
__global__ __launch_bounds__(512, 1) void proj_fused(
    const __half* __restrict__ A,
    const __half* __restrict__ Bt,
    const float* __restrict__ bias,
    const float* __restrict__ gamma,
    const float* __restrict__ beta,
    float* __restrict__ dstF,
    __half* __restrict__ hTout)
{
    extern __shared__ char smem[];
    const uint32_t sb = smem_u32(smem);
    const int tid  = threadIdx.x;
    const int wid  = tid >> 5;
    const int lane = tid & 31;
    const int bm   = blockIdx.x * 128;
    const int b    = bm >> 11;

    const int wm = (wid & 1) * 64;
    const int wn = (wid >> 1) * 32;
    const int tr   = lane & 7;
    const int sel  = lane >> 3;
    const int aRow = (sel & 1) * 8;
    const int aKf  = sel >> 1;
    const int bKf  = sel & 1;

    float acc[4][4][4];
#pragma unroll
    for (int a = 0; a < 4; a++)
#pragma unroll
        for (int x = 0; x < 4; x++)
#pragma unroll
            for (int c = 0; c < 4; c++) acc[a][x][c] = 0.f;

    auto load_chunk = [&](int i, int buf) {
        const uint32_t aBase = sb + (uint32_t)buf * 16384u;
        const uint32_t bBase = sb + 49152u + (uint32_t)buf * 32768u;
#pragma unroll
        for (int q = 0; q < 2; q++) {
            int f8 = tid + q * 512;
            int r  = f8 >> 3;
            int cf = f8 & 7;
            cp16(aBase + (uint32_t)(r * 128 + 16 * (cf ^ (r & 7))),
                 A + (long)(bm + r) * FF + i * KC + cf * 8);
        }
#pragma unroll
        for (int q = 0; q < 4; q++) {
            int f8 = tid + q * 512;
            int r  = f8 >> 3;
            int cf = f8 & 7;
            cp16(bBase + (uint32_t)(r * 128 + 16 * (cf ^ (r & 7))),
                 Bt + (long)r * FF + i * KC + cf * 8);
        }
    };

    load_chunk(0, 0); cp_commit();
    load_chunk(1, 1); cp_commit();

    const int nch = FF / KC;   // 8
    int bufc = 0;
    for (int i = 0; i < nch; i++) {
        if (i + 1 < nch) cp_wait<1>(); else cp_wait<0>();
        __syncthreads();
        if (i + 2 < nch) {
            int bufn = bufc + 2; if (bufn >= 3) bufn -= 3;
            load_chunk(i + 2, bufn);
            cp_commit();
        }

        const uint32_t aB = sb + (uint32_t)bufc * 16384u;
        const uint32_t bB = sb + 49152u + (uint32_t)bufc * 32768u;
#pragma unroll
        for (int ks = 0; ks < 4; ks++) {
            uint32_t ar[4][4];
#pragma unroll
            for (int mt = 0; mt < 4; mt++) {
                int row = wm + mt * 16 + aRow + tr;
                ldsm_x4(ar[mt], aB + (uint32_t)(row * 128 + 16 * (((ks << 1) + aKf) ^ (row & 7))));
            }
            uint32_t br[4][2];
#pragma unroll
            for (int nt = 0; nt < 4; nt++) {
                int row = wn + nt * 8 + tr;
                ldsm_x2(br[nt], bB + (uint32_t)(row * 128 + 16 * (((ks << 1) + bKf) ^ (row & 7))));
            }
#pragma unroll
            for (int mt = 0; mt < 4; mt++)
#pragma unroll
                for (int nt = 0; nt < 4; nt++)
                    mma_f16(acc[mt][nt], ar[mt], br[nt]);
        }
        bufc++; if (bufc == 3) bufc = 0;
    }

    // LN epilogue
    float* spart = (float*)(smem + SP_OFF);
    float* qpart = (float*)(smem + QP_OFF);
    float* muS   = (float*)(smem + MU_OFF);
    float* rsS   = (float*)(smem + RS_OFF);
    const int wni = wid >> 1;

#pragma unroll
    for (int mt = 0; mt < 4; mt++) {
        float sl = 0.f, ql = 0.f, sh = 0.f, qh = 0.f;
#pragma unroll
        for (int nt = 0; nt < 4; nt++) {
            int c0 = wn + nt * 8 + 2 * (lane & 3);
            float b0 = bias[c0], b1 = bias[c0 + 1];
            float z0 = acc[mt][nt][0] + b0;
            float z1 = acc[mt][nt][1] + b1;
            float z2 = acc[mt][nt][2] + b0;
            float z3 = acc[mt][nt][3] + b1;
            acc[mt][nt][0] = z0; acc[mt][nt][1] = z1;
            acc[mt][nt][2] = z2; acc[mt][nt][3] = z3;
            sl += z0 + z1; ql += z0 * z0 + z1 * z1;
            sh += z2 + z3; qh += z2 * z2 + z3 * z3;
        }
        sl += __shfl_xor_sync(0xffffffffu, sl, 1);
        sl += __shfl_xor_sync(0xffffffffu, sl, 2);
        ql += __shfl_xor_sync(0xffffffffu, ql, 1);
        ql += __shfl_xor_sync(0xffffffffu, ql, 2);
        sh += __shfl_xor_sync(0xffffffffu, sh, 1);
        sh += __shfl_xor_sync(0xffffffffu, sh, 2);
        qh += __shfl_xor_sync(0xffffffffu, qh, 1);
        qh += __shfl_xor_sync(0xffffffffu, qh, 2);
        if ((lane & 3) == 0) {
            int rlo = wm + mt * 16 + (lane >> 2);
            spart[rlo * 8 + wni] = sl;
            qpart[rlo * 8 + wni] = ql;
            spart[(rlo + 8) * 8 + wni] = sh;
            qpart[(rlo + 8) * 8 + wni] = qh;
        }
    }
    __syncthreads();
    if (tid < 128) {
        float s = 0.f, q = 0.f;
#pragma unroll
        for (int j = 0; j < 8; j++) { s += spart[tid * 8 + j]; q += qpart[tid * 8 + j]; }
        float mu  = s * (1.0f / HH);
        float var = q * (1.0f / HH) - mu * mu;
        muS[tid] = mu;
        rsS[tid] = rsqrtf(var + LN_EPS);
    }
    __syncthreads();

    __half* tile = (__half*)smem;
    float* df = dstF + (long)bm * HH;

#pragma unroll
    for (int mt = 0; mt < 4; mt++) {
        int rl = wm + mt * 16 + (lane >> 2);
        int rh = rl + 8;
        float mul = muS[rl], rsl = rsS[rl];
        float muh = muS[rh], rsh = rsS[rh];
#pragma unroll
        for (int nt = 0; nt < 4; nt++) {
            int c0 = wn + nt * 8 + 2 * (lane & 3);
            float g0 = gamma[c0], g1 = gamma[c0 + 1];
            float e0 = beta[c0],  e1 = beta[c0 + 1];
            float y0 = fmaxf((acc[mt][nt][0] - mul) * rsl * g0 + e0, 0.f);
            float y1 = fmaxf((acc[mt][nt][1] - mul) * rsl * g1 + e1, 0.f);
            float y2 = fmaxf((acc[mt][nt][2] - muh) * rsh * g0 + e0, 0.f);
            float y3 = fmaxf((acc[mt][nt][3] - muh) * rsh * g1 + e1, 0.f);
            float2 vlo; vlo.x = y0; vlo.y = y1;
            float2 vhi; vhi.x = y2; vhi.y = y3;
            *(float2*)(df + (long)rl * HH + c0) = vlo;
            *(float2*)(df + (long)rh * HH + c0) = vhi;
            tile[(c0)     * 136 + rl] = __float2half_rn(y0);
            tile[(c0 + 1) * 136 + rl] = __float2half_rn(y1);
            tile[(c0)     * 136 + rh] = __float2half_rn(y2);
            tile[(c0 + 1) * 136 + rh] = __float2half_rn(y3);
        }
    }

    __syncthreads();
    {
        int c  = tid & 255;
        int hs = tid >> 8;
        __half* dst = hTout + ((size_t)b * HH + c) * NN + (bm & (NN - 1)) + hs * 64;
        const uint4* src = (const uint4*)(tile + c * 136 + hs * 64);
#pragma unroll
        for (int g = 0; g < 8; g++)
            ((uint4*)dst)[g] = src[g];
    }
}

// ---------------------------------------------------------------------------
// Kernel 4: PERSISTENT 3-LAYER GNN. grid (16, 8) = 128 CTAs, 1/SM, co-resident.
// Loops layers with device-wide barriers between them.
// ---------------------------------------------------------------------------
__global__ __launch_bounds__(512, 1) void layers3_fused(
    const __half* __restrict__ NA,
    __half* __restrict__ hTa,
    __half* __restrict__ hTb,
    const __half* __restrict__ wlT,
    const float* __restrict__ bvec,
    const float* __restrict__ gammas,
    const float* __restrict__ betas,
    float* __restrict__ hres,
    float* __restrict__ outF)
{
    extern __shared__ char smem[];
    const uint32_t sb = smem_u32(smem);
    const int tid  = threadIdx.x;
    const int wid  = tid >> 5;
    const int lane = tid & 31;
    const int bm   = blockIdx.x * 128;
    const int b    = blockIdx.y;

    const __half* A = NA + (size_t)b * NN * NN;

    const int wm = (wid & 1) * 64;
    const int wn = (wid >> 1) * 32;
    const int tr   = lane & 7;
    const int sel  = lane >> 3;
    const int aRow = (sel & 1) * 8;
    const int aKf  = sel >> 1;
    const int bKf  = sel & 1;

#pragma unroll 1
    for (int l = 0; l < LL; l++) {
        const bool last = (l == LL - 1);
        const __half* Bt    = (l & 1 ? hTb : hTa) + (size_t)b * HH * NN;
        __half* hTout       = last ? nullptr : ((l & 1 ? hTa : hTb) + (size_t)b * HH * NN);
        const __half* Wt    = wlT + (long)l * HH * HH;
        const float* bias   = bvec + (long)l * HH;
        const float* gamma  = gammas + (long)l * HH;
        const float* beta   = betas + (long)l * HH;
        float* dstF         = last ? outF : hres;

        float acc[4][4][4];
#pragma unroll
        for (int a = 0; a < 4; a++)
#pragma unroll
            for (int x = 0; x < 4; x++)
#pragma unroll
                for (int c = 0; c < 4; c++) acc[a][x][c] = 0.f;

        auto load_chunk = [&](int i, int buf) {
            const uint32_t aBase = sb + (uint32_t)buf * 16384u;
            const uint32_t bBase = sb + 49152u + (uint32_t)buf * 32768u;
#pragma unroll
            for (int q = 0; q < 2; q++) {
                int f8 = tid + q * 512;
                int r  = f8 >> 3;
                int cf = f8 & 7;
                cp16(aBase + (uint32_t)(r * 128 + 16 * (cf ^ (r & 7))),
                     A + (long)(bm + r) * NN + i * KC + cf * 8);
            }
#pragma unroll
            for (int q = 0; q < 4; q++) {
                int f8 = tid + q * 512;
                int r  = f8 >> 3;
                int cf = f8 & 7;
                cp16(bBase + (uint32_t)(r * 128 + 16 * (cf ^ (r & 7))),
                     Bt + (long)r * NN + i * KC + cf * 8);
            }
        };

        load_chunk(0, 0); cp_commit();
        load_chunk(1, 1); cp_commit();

        const int nch = NN / KC;   // 32
        int bufc = 0;
        for (int i = 0; i < nch; i++) {
            if (i + 1 < nch) cp_wait<1>(); else cp_wait<0>();
            __syncthreads();
            if (i + 2 < nch) {
                int bufn = bufc + 2; if (bufn >= 3) bufn -= 3;
                load_chunk(i + 2, bufn);
                cp_commit();
            }

            const uint32_t aB = sb + (uint32_t)bufc * 16384u;
            const uint32_t bB = sb + 49152u + (uint32_t)bufc * 32768u;
#pragma unroll
            for (int ks = 0; ks < 4; ks++) {
                uint32_t ar[4][4];
#pragma unroll
                for (int mt = 0; mt < 4; mt++) {
                    int row = wm + mt * 16 + aRow + tr;
                    ldsm_x4(ar[mt], aB + (uint32_t)(row * 128 + 16 * (((ks << 1) + aKf) ^ (row & 7))));
                }
                uint32_t br[4][2];
#pragma unroll
                for (int nt = 0; nt < 4; nt++) {
                    int row = wn + nt * 8 + tr;
                    ldsm_x2(br[nt], bB + (uint32_t)(row * 128 + 16 * (((ks << 1) + bKf) ^ (row & 7))));
                }
#pragma unroll
                for (int mt = 0; mt < 4; mt++)
#pragma unroll
                    for (int nt = 0; nt < 4; nt++)
                        mma_f16(acc[mt][nt], ar[mt], br[nt]);
            }
            bufc++; if (bufc == 3) bufc = 0;
        }
        __syncthreads();   // fence phase-1 smem reads before phase-2 overwrites

        // phase 2 staging: W[l]^T into 4 chunk buffers at region0
#pragma unroll
        for (int q = 0; q < 16; q++) {
            int u     = tid + q * 512;
            int chunk = u >> 11;
            int v     = u & 2047;
            int r     = v >> 3;
            int cf    = v & 7;
            cp16(sb + (uint32_t)(chunk * 32768 + r * 128 + 16 * (cf ^ (r & 7))),
                 Wt + (long)r * 256 + chunk * 64 + cf * 8);
        }
        cp_commit();

        {
            const uint32_t a2base = sb + A2_OFF + (uint32_t)(wn >> 6) * 16384u;
            const int ubase = (wn & 32) >> 3;
            const uint32_t coff = (uint32_t)(4 * (lane & 3));
#pragma unroll
            for (int mt = 0; mt < 4; mt++) {
                int rlo = wm + mt * 16 + (lane >> 2);
                int rhi = rlo + 8;
#pragma unroll
                for (int nt = 0; nt < 4; nt++) {
                    int u = ubase + nt;
                    uint32_t alo = a2base + (uint32_t)(rlo * 128 + 16 * (u ^ (rlo & 7))) + coff;
                    uint32_t ahi = a2base + (uint32_t)(rhi * 128 + 16 * (u ^ (rhi & 7))) + coff;
                    *(__half2*)(smem + (alo - sb)) = __floats2half2_rn(acc[mt][nt][0], acc[mt][nt][1]);
                    *(__half2*)(smem + (ahi - sb)) = __floats2half2_rn(acc[mt][nt][2], acc[mt][nt][3]);
                }
            }
        }
        cp_wait<0>();
        __syncthreads();

        // phase 2 mainloop (4 resident chunks, K=256)
        float acc2[4][4][4];
#pragma unroll
        for (int a = 0; a < 4; a++)
#pragma unroll
            for (int x = 0; x < 4; x++)
#pragma unroll
                for (int c = 0; c < 4; c++) acc2[a][x][c] = 0.f;

#pragma unroll
        for (int i = 0; i < 4; i++) {
            const uint32_t aB = sb + A2_OFF + (uint32_t)i * 16384u;
            const uint32_t bB = sb + (uint32_t)i * 32768u;
#pragma unroll
            for (int ks = 0; ks < 4; ks++) {
                uint32_t ar[4][4];
#pragma unroll
                for (int mt = 0; mt < 4; mt++) {
                    int row = wm + mt * 16 + aRow + tr;
                    ldsm_x4(ar[mt], aB + (uint32_t)(row * 128 + 16 * (((ks << 1) + aKf) ^ (row & 7))));
                }
                uint32_t br[4][2];
#pragma unroll
                for (int nt = 0; nt < 4; nt++) {
                    int row = wn + nt * 8 + tr;
                    ldsm_x2(br[nt], bB + (uint32_t)(row * 128 + 16 * (((ks << 1) + bKf) ^ (row & 7))));
                }
#pragma unroll
                for (int mt = 0; mt < 4; mt++)
#pragma unroll
                    for (int nt = 0; nt < 4; nt++)
                        mma_f16(acc2[mt][nt], ar[mt], br[nt]);
            }
        }
        __syncthreads();

        // phase 3: LN epilogue
        float* spart = (float*)(smem + SP_OFF);
        float* qpart = (float*)(smem + QP_OFF);
        float* muS   = (float*)(smem + MU_OFF);
        float* rsS   = (float*)(smem + RS_OFF);
        const int wni = wid >> 1;

#pragma unroll
        for (int mt = 0; mt < 4; mt++) {
            float sl = 0.f, ql = 0.f, sh = 0.f, qh = 0.f;
#pragma unroll
            for (int nt = 0; nt < 4; nt++) {
                int c0 = wn + nt * 8 + 2 * (lane & 3);
                float b0 = bias[c0], b1 = bias[c0 + 1];
                float z0 = acc2[mt][nt][0] + b0;
                float z1 = acc2[mt][nt][1] + b1;
                float z2 = acc2[mt][nt][2] + b0;
                float z3 = acc2[mt][nt][3] + b1;
                acc2[mt][nt][0] = z0; acc2[mt][nt][1] = z1;
                acc2[mt][nt][2] = z2; acc2[mt][nt][3] = z3;
                sl += z0 + z1; ql += z0 * z0 + z1 * z1;
                sh += z2 + z3; qh += z2 * z2 + z3 * z3;
            }
            sl += __shfl_xor_sync(0xffffffffu, sl, 1);
            sl += __shfl_xor_sync(0xffffffffu, sl, 2);
            ql += __shfl_xor_sync(0xffffffffu, ql, 1);
            ql += __shfl_xor_sync(0xffffffffu, ql, 2);
            sh += __shfl_xor_sync(0xffffffffu, sh, 1);
            sh += __shfl_xor_sync(0xffffffffu, sh, 2);
            qh += __shfl_xor_sync(0xffffffffu, qh, 1);
            qh += __shfl_xor_sync(0xffffffffu, qh, 2);
            if ((lane & 3) == 0) {
                int rlo = wm + mt * 16 + (lane >> 2);
                spart[rlo * 8 + wni] = sl;
                qpart[rlo * 8 + wni] = ql;
                spart[(rlo + 8) * 8 + wni] = sh;
                qpart[(rlo + 8) * 8 + wni] = qh;
            }
        }
        __syncthreads();
        if (tid < 128) {
            float s = 0.f, q = 0.f;
#pragma unroll
            for (int j = 0; j < 8; j++) { s += spart[tid * 8 + j]; q += qpart[tid * 8 + j]; }
            float mu  = s * (1.0f / HH);
            float var = q * (1.0f / HH) - mu * mu;
            muS[tid] = mu;
            rsS[tid] = rsqrtf(var + LN_EPS);
        }
        __syncthreads();

        __half* tile = (__half*)smem;
        const bool doT = (hTout != nullptr);
        float* hr = hres + ((size_t)b * NN + bm) * HH;
        float* df = dstF + ((size_t)b * NN + bm) * HH;

#pragma unroll
        for (int mt = 0; mt < 4; mt++) {
            int rl = wm + mt * 16 + (lane >> 2);
            int rh = rl + 8;
            float mul = muS[rl], rsl = rsS[rl];
            float muh = muS[rh], rsh = rsS[rh];
#pragma unroll
            for (int nt = 0; nt < 4; nt++) {
                int c0 = wn + nt * 8 + 2 * (lane & 3);
                float g0 = gamma[c0], g1 = gamma[c0 + 1];
                float e0 = beta[c0],  e1 = beta[c0 + 1];
                float y0 = fmaxf((acc2[mt][nt][0] - mul) * rsl * g0 + e0, 0.f) + hr[(long)rl * HH + c0];
                float y1 = fmaxf((acc2[mt][nt][1] - mul) * rsl * g1 + e1, 0.f) + hr[(long)rl * HH + c0 + 1];
                float y2 = fmaxf((acc2[mt][nt][2] - muh) * rsh * g0 + e0, 0.f) + hr[(long)rh * HH + c0];
                float y3 = fmaxf((acc2[mt][nt][3] - muh) * rsh * g1 + e1, 0.f) + hr[(long)rh * HH + c0 + 1];
                float2 vlo; vlo.x = y0; vlo.y = y1;
                float2 vhi; vhi.x = y2; vhi.y = y3;
                *(float2*)(df + (long)rl * HH + c0) = vlo;
                *(float2*)(df + (long)rh * HH + c0) = vhi;
                if (doT) {
                    tile[(c0)     * 136 + rl] = __float2half_rn(y0);
                    tile[(c0 + 1) * 136 + rl] = __float2half_rn(y1);
                    tile[(c0)     * 136 + rh] = __float2half_rn(y2);
                    tile[(c0 + 1) * 136 + rh] = __float2half_rn(y3);
                }
            }
        }

        if (doT) {
            __syncthreads();
            int c  = tid & 255;
            int hs = tid >> 8;
            __half* dst = hTout + (long)c * NN + bm + hs * 64;
            const uint4* src = (const uint4*)(tile + c * 136 + hs * 64);
#pragma unroll
            for (int g = 0; g < 8; g++)
                ((uint4*)dst)[g] = src[g];
        }

        // device-wide barrier before next layer reads hT (skip after last)
        if (!last) grid_barrier(l);
    }
}

// ---------------------------------------------------------------------------
// Launch orchestration (R9 schedule + persistent layers)
// ---------------------------------------------------------------------------
extern "C" void kernel_launch(void* const* d_in, const int* in_sizes, int n_in,
                              void* d_out, int out_size)
{
    const float* node_feat = (const float*)d_in[0];
    const float* edge_w    = (const float*)d_in[1];
    const float* adj       = (const float*)d_in[2];
    const float* W_in      = (const float*)d_in[3];
    const float* b_in      = (const float*)d_in[4];
    const float* g_in      = (const float*)d_in[5];
    const float* bt_in     = (const float*)d_in[6];
    const float* W         = (const float*)d_in[7];
    const float* bvec      = (const float*)d_in[8];
    const float* gamma     = (const float*)d_in[9];
    const float* beta      = (const float*)d_in[10];
    float* out = (float*)d_out;

    __half *na_p, *nf_p, *hTa_p, *hTb_p, *wT_p;
    float *h_p;
    cudaGetSymbolAddress((void**)&na_p,  g_norm_adj);
    cudaGetSymbolAddress((void**)&nf_p,  g_nf);
    cudaGetSymbolAddress((void**)&h_p,   g_h);
    cudaGetSymbolAddress((void**)&hTa_p, g_hTa);
    cudaGetSymbolAddress((void**)&hTb_p, g_hTb);
    cudaGetSymbolAddress((void**)&wT_p,  g_wT);

    cudaFuncSetAttribute(proj_fused,    cudaFuncAttributeMaxDynamicSharedMemorySize, FUSED_SMEM);
    cudaFuncSetAttribute(layers3_fused, cudaFuncAttributeMaxDynamicSharedMemorySize, FUSED_SMEM);

    // ONE side stream + 2 events (footprint proven safe in round 9)
    static cudaStream_t s_side = nullptr;
    static cudaEvent_t  s_fork = nullptr, s_join = nullptr;
    static bool s_init = false;
    if (!s_init) {
        s_init = true;
        if (cudaStreamCreateWithFlags(&s_side, cudaStreamNonBlocking) != cudaSuccess)
            s_side = nullptr;
        if (s_side) {
            if (cudaEventCreateWithFlags(&s_fork, cudaEventDisableTiming) != cudaSuccess ||
                cudaEventCreateWithFlags(&s_join, cudaEventDisableTiming) != cudaSuccess)
                s_side = nullptr;
        }
    }
    const bool multi = (s_side != nullptr);
    cudaStream_t side = multi ? s_side : (cudaStream_t)0;

    const int M_all = BB * NN;
    __half* winT = wT_p;
    __half* wlT  = wT_p + 256 * 512;

    if (multi) {
        cudaEventRecord(s_fork, 0);
        cudaStreamWaitEvent(side, s_fork, 0);
    }

    // main stream: normalized adjacency (DRAM-bound, ~56us)
    norm_adj_kernel<<<dim3(NN, BB), 256>>>(
        (const float4*)adj, (const float4*)edge_w, na_p);

    // side stream: weights + node_feat conversion + fused projection
    transpose_kernel<<<dim3(HH / 32, FF / 32, 1), dim3(32, 8), 0, side>>>(
        W_in, winT, FF, HH, 0, 0);
    transpose_kernel<<<dim3(HH / 32, HH / 32, LL), dim3(32, 8), 0, side>>>(
        W, wlT, HH, HH, (long)HH * HH, (long)HH * HH);
    half_copy_kernel<<<(int)(((long)M_all * FF / 4) / 256), 256, 0, side>>>(
        (const float4*)node_feat, (__half2*)nf_p);
    proj_fused<<<dim3(M_all / 128, 1), 512, FUSED_SMEM, side>>>(
        nf_p, winT, b_in, g_in, bt_in, h_p, hTa_p);

    if (multi) {
        cudaEventRecord(s_join, side);
        cudaStreamWaitEvent((cudaStream_t)0, s_join, 0);
    }

    // persistent 3-layer kernel (main stream): 128 co-resident CTAs
    layers3_fused<<<dim3(NN / 128, BB), 512, FUSED_SMEM>>>(
        na_p, hTa_p, hTb_p, wlT, bvec, gamma, beta, h_p, out);
}

// round 17
// speedup vs baseline: 1.0038x; 1.0038x over previous
#include <cuda_runtime.h>
#include <cuda_fp16.h>
#include <math.h>
#include <stdint.h>

// Problem constants
#define BB 8
#define NN 2048
#define FF 512
#define HH 256
#define LL 3
#define LN_EPS 1e-5f
#define NCTA 128            // layer kernel grid size (16 x 8), 1 CTA/SM

// ---------------------------------------------------------------------------
// Device scratch (static — no cudaMalloc allowed)
// ---------------------------------------------------------------------------
__device__ __align__(128) __half g_norm_adj[(size_t)BB * NN * NN];   // 67 MB
__device__ __align__(128) __half g_nf[(size_t)BB * NN * FF];         // 16.8 MB
__device__ __align__(128) float  g_h[(size_t)BB * NN * HH];          // fp32 residual
__device__ __align__(128) __half g_hTa[(size_t)BB * HH * NN];        // hT ping
__device__ __align__(128) __half g_hTb[(size_t)BB * HH * NN];        // hT pong
__device__ __align__(128) __half g_wT[256 * 512 + 3 * 256 * 256];    // W_in^T, W[l]^T

// grid barrier state (replay-safe: gen is monotonic, count self-resets)
__device__ unsigned g_bar_count[4];
__device__ unsigned g_bar_gen[4];

// ---------------------------------------------------------------------------
// Helpers
// ---------------------------------------------------------------------------
__device__ __forceinline__ uint32_t smem_u32(const void* p) {
    uint32_t a;
    asm("{ .reg .u64 t; cvta.to.shared.u64 t, %1; cvt.u32.u64 %0, t; }" : "=r"(a) : "l"(p));
    return a;
}
__device__ __forceinline__ void cp16(uint32_t dst, const void* src) {
    asm volatile("cp.async.cg.shared.global [%0], [%1], 16;" :: "r"(dst), "l"(src) : "memory");
}
__device__ __forceinline__ void cp_commit() {
    asm volatile("cp.async.commit_group;" ::: "memory");
}
template <int N> __device__ __forceinline__ void cp_wait() {
    asm volatile("cp.async.wait_group %0;" :: "n"(N) : "memory");
}
__device__ __forceinline__ void ldsm_x4(uint32_t* r, uint32_t addr) {
    asm volatile("ldmatrix.sync.aligned.m8n8.x4.shared.b16 {%0,%1,%2,%3}, [%4];"
                 : "=r"(r[0]), "=r"(r[1]), "=r"(r[2]), "=r"(r[3]) : "r"(addr));
}
__device__ __forceinline__ void ldsm_x2(uint32_t* r, uint32_t addr) {
    asm volatile("ldmatrix.sync.aligned.m8n8.x2.shared.b16 {%0,%1}, [%2];"
                 : "=r"(r[0]), "=r"(r[1]) : "r"(addr));
}
__device__ __forceinline__ void mma_f16(float* c, const uint32_t* a, const uint32_t* b) {
    asm volatile("mma.sync.aligned.m16n8k16.row.col.f32.f16.f16.f32 "
                 "{%0,%1,%2,%3}, {%4,%5,%6,%7}, {%8,%9}, {%0,%1,%2,%3};"
                 : "+f"(c[0]), "+f"(c[1]), "+f"(c[2]), "+f"(c[3])
                 : "r"(a[0]), "r"(a[1]), "r"(a[2]), "r"(a[3]), "r"(b[0]), "r"(b[1]));
}

// Device-wide barrier: all NCTA CTAs must be co-resident (they are: 1 CTA/SM).
__device__ __forceinline__ void grid_barrier(int id) {
    __syncthreads();
    if (threadIdx.x == 0) {
        __threadfence();
        unsigned gen = *(volatile unsigned*)&g_bar_gen[id];
        if (atomicAdd(&g_bar_count[id], 1u) == NCTA - 1) {
            g_bar_count[id] = 0;
            __threadfence();
            atomicAdd(&g_bar_gen[id], 1u);
        } else {
            while (*(volatile unsigned*)&g_bar_gen[id] == gen) { }
        }
    }
    __syncthreads();
}

// smem region offsets for fused kernels
#define KC 64
#define A2_OFF    147456u
#define SP_OFF    (A2_OFF + 65536u)
#define QP_OFF    (SP_OFF + 4096u)
#define MU_OFF    (QP_OFF + 4096u)
#define RS_OFF    (MU_OFF + 512u)
#define FUSED_SMEM (RS_OFF + 512u)

// ---------------------------------------------------------------------------
// Kernel 1: normalized adjacency -> fp16 (grid (NN, BB))
// ---------------------------------------------------------------------------
__global__ __launch_bounds__(256) void norm_adj_kernel(
    const float4* __restrict__ adj, const float4* __restrict__ ew,
    __half* __restrict__ out)
{
    const int row = blockIdx.x;
    const int b   = blockIdx.y;
    const long base4 = ((long)b * NN + row) * (NN / 4);
    const float4* __restrict__ arow = adj + base4;
    const float4* __restrict__ erow = ew + base4;
    __half2* __restrict__ orow = (__half2*)(out + ((long)b * NN + row) * NN);

    __shared__ float4 w4[NN / 4];
    __shared__ float sbuf[8];

    const int diag4 = row >> 2;
    const int diagc = row & 3;

    float lsum = 0.f;
#pragma unroll
    for (int i = 0; i < 2; i++) {
        int c4 = threadIdx.x + i * 256;
        float4 a = arow[c4];
        float4 e = erow[c4];
        if (c4 == diag4) {
            if (diagc == 0) a.x += 1.f;
            else if (diagc == 1) a.y += 1.f;
            else if (diagc == 2) a.z += 1.f;
            else a.w += 1.f;
        }
        float4 v;
        v.x = fminf(a.x, 1.f) * e.x;
        v.y = fminf(a.y, 1.f) * e.y;
        v.z = fminf(a.z, 1.f) * e.z;
        v.w = fminf(a.w, 1.f) * e.w;
        w4[c4] = v;
        lsum += v.x + v.y + v.z + v.w;
    }
#pragma unroll
    for (int o = 16; o > 0; o >>= 1) lsum += __shfl_down_sync(0xffffffffu, lsum, o);
    int lane = threadIdx.x & 31, wid = threadIdx.x >> 5;
    if (lane == 0) sbuf[wid] = lsum;
    __syncthreads();
    if (wid == 0) {
        float v = (lane < 8) ? sbuf[lane] : 0.f;
#pragma unroll
        for (int o = 4; o > 0; o >>= 1) v += __shfl_down_sync(0xffffffffu, v, o);
        if (lane == 0) sbuf[0] = v;
    }
    __syncthreads();
    const float inv = 1.0f / (sbuf[0] + 1e-8f);

#pragma unroll
    for (int i = 0; i < 2; i++) {
        int c4 = threadIdx.x + i * 256;
        float4 v = w4[c4];
        orow[2 * c4 + 0] = __floats2half2_rn(v.x * inv, v.y * inv);
        orow[2 * c4 + 1] = __floats2half2_rn(v.z * inv, v.w * inv);
    }
}

// ---------------------------------------------------------------------------
// Kernel 2: 32x32 transpose, fp32 -> fp16 (weights)
// ---------------------------------------------------------------------------
__global__ __launch_bounds__(256) void transpose_kernel(
    const float* __restrict__ in, __half* __restrict__ out,
    int R, int C, long sIn, long sOut)
{
    __shared__ float tile[32][33];
    const int bz = blockIdx.z;
    in  += (long)bz * sIn;
    out += (long)bz * sOut;
    const int c0 = blockIdx.x * 32;
    const int r0 = blockIdx.y * 32;
    const int tx = threadIdx.x, ty = threadIdx.y;
#pragma unroll
    for (int i = 0; i < 4; i++)
        tile[ty + i * 8][tx] = in[(long)(r0 + ty + i * 8) * C + c0 + tx];
    __syncthreads();
#pragma unroll
    for (int i = 0; i < 4; i++)
        out[(long)(c0 + ty + i * 8) * R + r0 + tx] = __float2half_rn(tile[tx][ty + i * 8]);
}

// ---------------------------------------------------------------------------
// Kernel 2b: fp32 -> fp16 copy (node_feat)
// ---------------------------------------------------------------------------
__global__ __launch_bounds__(256) void half_copy_kernel(
    const float4* __restrict__ in, __half2* __restrict__ out)
{
    long i = (long)blockIdx.x * 256 + threadIdx.x;
    float4 v = in[i];
    out[2 * i + 0] = __floats2half2_rn(v.x, v.y);
    out[2 * i + 1] = __floats2half2_rn(v.z, v.w);
}

// ---------------------------------------------------------------------------
// Kernel 3: FUSED INPUT PROJECTION (GEMM K=512 + LN epilogue), grid (128)
// ---------------------------------------------------------------------------
__global__ __launch_bounds__(512, 1) void proj_fused(
    const __half* __restrict__ A,
    const __half* __restrict__ Bt,
    const float* __restrict__ bias,
    const float* __restrict__ gamma,
    const float* __restrict__ beta,
    float* __restrict__ dstF,
    __half* __restrict__ hTout)
{
    extern __shared__ char smem[];
    const uint32_t sb = smem_u32(smem);
    const int tid  = threadIdx.x;
    const int wid  = tid >> 5;
    const int lane = tid & 31;
    const int bm   = blockIdx.x * 128;
    const int b    = bm >> 11;

    const int wm = (wid & 1) * 64;
    const int wn = (wid >> 1) * 32;
    const int tr   = lane & 7;
    const int sel  = lane >> 3;
    const int aRow = (sel & 1) * 8;
    const int aKf  = sel >> 1;
    const int bKf  = sel & 1;

    float acc[4][4][4];
#pragma unroll
    for (int a = 0; a < 4; a++)
#pragma unroll
        for (int x = 0; x < 4; x++)
#pragma unroll
            for (int c = 0; c < 4; c++) acc[a][x][c] = 0.f;

    auto load_chunk = [&](int i, int buf) {
        const uint32_t aBase = sb + (uint32_t)buf * 16384u;
        const uint32_t bBase = sb + 49152u + (uint32_t)buf * 32768u;
#pragma unroll
        for (int q = 0; q < 2; q++) {
            int f8 = tid + q * 512;
            int r  = f8 >> 3;
            int cf = f8 & 7;
            cp16(aBase + (uint32_t)(r * 128 + 16 * (cf ^ (r & 7))),
                 A + (long)(bm + r) * FF + i * KC + cf * 8);
        }
#pragma unroll
        for (int q = 0; q < 4; q++) {
            int f8 = tid + q * 512;
            int r  = f8 >> 3;
            int cf = f8 & 7;
            cp16(bBase + (uint32_t)(r * 128 + 16 * (cf ^ (r & 7))),
                 Bt + (long)r * FF + i * KC + cf * 8);
        }
    };

    load_chunk(0, 0); cp_commit();
    load_chunk(1, 1); cp_commit();

    const int nch = FF / KC;   // 8
    int bufc = 0;
    for (int i = 0; i < nch; i++) {
        if (i + 1 < nch) cp_wait<1>(); else cp_wait<0>();
        __syncthreads();
        if (i + 2 < nch) {
            int bufn = bufc + 2; if (bufn >= 3) bufn -= 3;
            load_chunk(i + 2, bufn);
            cp_commit();
        }

        const uint32_t aB = sb + (uint32_t)bufc * 16384u;
        const uint32_t bB = sb + 49152u + (uint32_t)bufc * 32768u;
#pragma unroll
        for (int ks = 0; ks < 4; ks++) {
            uint32_t ar[4][4];
#pragma unroll
            for (int mt = 0; mt < 4; mt++) {
                int row = wm + mt * 16 + aRow + tr;
                ldsm_x4(ar[mt], aB + (uint32_t)(row * 128 + 16 * (((ks << 1) + aKf) ^ (row & 7))));
            }
            uint32_t br[4][2];
#pragma unroll
            for (int nt = 0; nt < 4; nt++) {
                int row = wn + nt * 8 + tr;
                ldsm_x2(br[nt], bB + (uint32_t)(row * 128 + 16 * (((ks << 1) + bKf) ^ (row & 7))));
            }
#pragma unroll
            for (int mt = 0; mt < 4; mt++)
#pragma unroll
                for (int nt = 0; nt < 4; nt++)
                    mma_f16(acc[mt][nt], ar[mt], br[nt]);
        }
        bufc++; if (bufc == 3) bufc = 0;
    }

    // LN epilogue
    float* spart = (float*)(smem + SP_OFF);
    float* qpart = (float*)(smem + QP_OFF);
    float* muS   = (float*)(smem + MU_OFF);
    float* rsS   = (float*)(smem + RS_OFF);
    const int wni = wid >> 1;

#pragma unroll
    for (int mt = 0; mt < 4; mt++) {
        float sl = 0.f, ql = 0.f, sh = 0.f, qh = 0.f;
#pragma unroll
        for (int nt = 0; nt < 4; nt++) {
            int c0 = wn + nt * 8 + 2 * (lane & 3);
            float b0 = bias[c0], b1 = bias[c0 + 1];
            float z0 = acc[mt][nt][0] + b0;
            float z1 = acc[mt][nt][1] + b1;
            float z2 = acc[mt][nt][2] + b0;
            float z3 = acc[mt][nt][3] + b1;
            acc[mt][nt][0] = z0; acc[mt][nt][1] = z1;
            acc[mt][nt][2] = z2; acc[mt][nt][3] = z3;
            sl += z0 + z1; ql += z0 * z0 + z1 * z1;
            sh += z2 + z3; qh += z2 * z2 + z3 * z3;
        }
        sl += __shfl_xor_sync(0xffffffffu, sl, 1);
        sl += __shfl_xor_sync(0xffffffffu, sl, 2);
        ql += __shfl_xor_sync(0xffffffffu, ql, 1);
        ql += __shfl_xor_sync(0xffffffffu, ql, 2);
        sh += __shfl_xor_sync(0xffffffffu, sh, 1);
        sh += __shfl_xor_sync(0xffffffffu, sh, 2);
        qh += __shfl_xor_sync(0xffffffffu, qh, 1);
        qh += __shfl_xor_sync(0xffffffffu, qh, 2);
        if ((lane & 3) == 0) {
            int rlo = wm + mt * 16 + (lane >> 2);
            spart[rlo * 8 + wni] = sl;
            qpart[rlo * 8 + wni] = ql;
            spart[(rlo + 8) * 8 + wni] = sh;
            qpart[(rlo + 8) * 8 + wni] = qh;
        }
    }
    __syncthreads();
    if (tid < 128) {
        float s = 0.f, q = 0.f;
#pragma unroll
        for (int j = 0; j < 8; j++) { s += spart[tid * 8 + j]; q += qpart[tid * 8 + j]; }
        float mu  = s * (1.0f / HH);
        float var = q * (1.0f / HH) - mu * mu;
        muS[tid] = mu;
        rsS[tid] = rsqrtf(var + LN_EPS);
    }
    __syncthreads();

    __half* tile = (__half*)smem;
    float* df = dstF + (long)bm * HH;

#pragma unroll
    for (int mt = 0; mt < 4; mt++) {
        int rl = wm + mt * 16 + (lane >> 2);
        int rh = rl + 8;
        float mul = muS[rl], rsl = rsS[rl];
        float muh = muS[rh], rsh = rsS[rh];
#pragma unroll
        for (int nt = 0; nt < 4; nt++) {
            int c0 = wn + nt * 8 + 2 * (lane & 3);
            float g0 = gamma[c0], g1 = gamma[c0 + 1];
            float e0 = beta[c0],  e1 = beta[c0 + 1];
            float y0 = fmaxf((acc[mt][nt][0] - mul) * rsl * g0 + e0, 0.f);
            float y1 = fmaxf((acc[mt][nt][1] - mul) * rsl * g1 + e1, 0.f);
            float y2 = fmaxf((acc[mt][nt][2] - muh) * rsh * g0 + e0, 0.f);
            float y3 = fmaxf((acc[mt][nt][3] - muh) * rsh * g1 + e1, 0.f);
            float2 vlo; vlo.x = y0; vlo.y = y1;
            float2 vhi; vhi.x = y2; vhi.y = y3;
            *(float2*)(df + (long)rl * HH + c0) = vlo;
            *(float2*)(df + (long)rh * HH + c0) = vhi;
            tile[(c0)     * 136 + rl] = __float2half_rn(y0);
            tile[(c0 + 1) * 136 + rl] = __float2half_rn(y1);
            tile[(c0)     * 136 + rh] = __float2half_rn(y2);
            tile[(c0 + 1) * 136 + rh] = __float2half_rn(y3);
        }
    }

    __syncthreads();
    {
        int c  = tid & 255;
        int hs = tid >> 8;
        __half* dst = hTout + ((size_t)b * HH + c) * NN + (bm & (NN - 1)) + hs * 64;
        const uint4* src = (const uint4*)(tile + c * 136 + hs * 64);
#pragma unroll
        for (int g = 0; g < 8; g++)
            ((uint4*)dst)[g] = src[g];
    }
}

// ---------------------------------------------------------------------------
// Kernel 4: PERSISTENT 3-LAYER GNN. grid (16, 8) = 128 CTAs, 1/SM, co-resident.
// Loops layers with device-wide barriers between them.
// ---------------------------------------------------------------------------
__global__ __launch_bounds__(512, 1) void layers3_fused(
    const __half* __restrict__ NA,
    __half* __restrict__ hTa,
    __half* __restrict__ hTb,
    const __half* __restrict__ wlT,
    const float* __restrict__ bvec,
    const float* __restrict__ gammas,
    const float* __restrict__ betas,
    float* __restrict__ hres,
    float* __restrict__ outF)
{
    extern __shared__ char smem[];
    const uint32_t sb = smem_u32(smem);
    const int tid  = threadIdx.x;
    const int wid  = tid >> 5;
    const int lane = tid & 31;
    const int bm   = blockIdx.x * 128;
    const int b    = blockIdx.y;

    const __half* A = NA + (size_t)b * NN * NN;

    const int wm = (wid & 1) * 64;
    const int wn = (wid >> 1) * 32;
    const int tr   = lane & 7;
    const int sel  = lane >> 3;
    const int aRow = (sel & 1) * 8;
    const int aKf  = sel >> 1;
    const int bKf  = sel & 1;

#pragma unroll 1
    for (int l = 0; l < LL; l++) {
        const bool last = (l == LL - 1);
        const __half* Bt    = (l & 1 ? hTb : hTa) + (size_t)b * HH * NN;
        __half* hTout       = last ? nullptr : ((l & 1 ? hTa : hTb) + (size_t)b * HH * NN);
        const __half* Wt    = wlT + (long)l * HH * HH;
        const float* bias   = bvec + (long)l * HH;
        const float* gamma  = gammas + (long)l * HH;
        const float* beta   = betas + (long)l * HH;
        float* dstF         = last ? outF : hres;

        float acc[4][4][4];
#pragma unroll
        for (int a = 0; a < 4; a++)
#pragma unroll
            for (int x = 0; x < 4; x++)
#pragma unroll
                for (int c = 0; c < 4; c++) acc[a][x][c] = 0.f;

        auto load_chunk = [&](int i, int buf) {
            const uint32_t aBase = sb + (uint32_t)buf * 16384u;
            const uint32_t bBase = sb + 49152u + (uint32_t)buf * 32768u;
#pragma unroll
            for (int q = 0; q < 2; q++) {
                int f8 = tid + q * 512;
                int r  = f8 >> 3;
                int cf = f8 & 7;
                cp16(aBase + (uint32_t)(r * 128 + 16 * (cf ^ (r & 7))),
                     A + (long)(bm + r) * NN + i * KC + cf * 8);
            }
#pragma unroll
            for (int q = 0; q < 4; q++) {
                int f8 = tid + q * 512;
                int r  = f8 >> 3;
                int cf = f8 & 7;
                cp16(bBase + (uint32_t)(r * 128 + 16 * (cf ^ (r & 7))),
                     Bt + (long)r * NN + i * KC + cf * 8);
            }
        };

        load_chunk(0, 0); cp_commit();
        load_chunk(1, 1); cp_commit();

        const int nch = NN / KC;   // 32
        int bufc = 0;
        for (int i = 0; i < nch; i++) {
            if (i + 1 < nch) cp_wait<1>(); else cp_wait<0>();
            __syncthreads();
            if (i + 2 < nch) {
                int bufn = bufc + 2; if (bufn >= 3) bufn -= 3;
                load_chunk(i + 2, bufn);
                cp_commit();
            }

            const uint32_t aB = sb + (uint32_t)bufc * 16384u;
            const uint32_t bB = sb + 49152u + (uint32_t)bufc * 32768u;
#pragma unroll
            for (int ks = 0; ks < 4; ks++) {
                uint32_t ar[4][4];
#pragma unroll
                for (int mt = 0; mt < 4; mt++) {
                    int row = wm + mt * 16 + aRow + tr;
                    ldsm_x4(ar[mt], aB + (uint32_t)(row * 128 + 16 * (((ks << 1) + aKf) ^ (row & 7))));
                }
                uint32_t br[4][2];
#pragma unroll
                for (int nt = 0; nt < 4; nt++) {
                    int row = wn + nt * 8 + tr;
                    ldsm_x2(br[nt], bB + (uint32_t)(row * 128 + 16 * (((ks << 1) + bKf) ^ (row & 7))));
                }
#pragma unroll
                for (int mt = 0; mt < 4; mt++)
#pragma unroll
                    for (int nt = 0; nt < 4; nt++)
                        mma_f16(acc[mt][nt], ar[mt], br[nt]);
            }
            bufc++; if (bufc == 3) bufc = 0;
        }
        __syncthreads();   // fence phase-1 smem reads before phase-2 overwrites

        // phase 2 staging: W[l]^T into 4 chunk buffers at region0
#pragma unroll
        for (int q = 0; q < 16; q++) {
            int u     = tid + q * 512;
            int chunk = u >> 11;
            int v     = u & 2047;
            int r     = v >> 3;
            int cf    = v & 7;
            cp16(sb + (uint32_t)(chunk * 32768 + r * 128 + 16 * (cf ^ (r & 7))),
                 Wt + (long)r * 256 + chunk * 64 + cf * 8);
        }
        cp_commit();

        {
            const uint32_t a2base = sb + A2_OFF + (uint32_t)(wn >> 6) * 16384u;
            const int ubase = (wn & 32) >> 3;
            const uint32_t coff = (uint32_t)(4 * (lane & 3));
#pragma unroll
            for (int mt = 0; mt < 4; mt++) {
                int rlo = wm + mt * 16 + (lane >> 2);
                int rhi = rlo + 8;
#pragma unroll
                for (int nt = 0; nt < 4; nt++) {
                    int u = ubase + nt;
                    uint32_t alo = a2base + (uint32_t)(rlo * 128 + 16 * (u ^ (rlo & 7))) + coff;
                    uint32_t ahi = a2base + (uint32_t)(rhi * 128 + 16 * (u ^ (rhi & 7))) + coff;
                    *(__half2*)(smem + (alo - sb)) = __floats2half2_rn(acc[mt][nt][0], acc[mt][nt][1]);
                    *(__half2*)(smem + (ahi - sb)) = __floats2half2_rn(acc[mt][nt][2], acc[mt][nt][3]);
                }
            }
        }
        cp_wait<0>();
        __syncthreads();

        // phase 2 mainloop (4 resident chunks, K=256)
        float acc2[4][4][4];
#pragma unroll
        for (int a = 0; a < 4; a++)
#pragma unroll
            for (int x = 0; x < 4; x++)
#pragma unroll
                for (int c = 0; c < 4; c++) acc2[a][x][c] = 0.f;

#pragma unroll
        for (int i = 0; i < 4; i++) {
            const uint32_t aB = sb + A2_OFF + (uint32_t)i * 16384u;
            const uint32_t bB = sb + (uint32_t)i * 32768u;
#pragma unroll
            for (int ks = 0; ks < 4; ks++) {
                uint32_t ar[4][4];
#pragma unroll
                for (int mt = 0; mt < 4; mt++) {
                    int row = wm + mt * 16 + aRow + tr;
                    ldsm_x4(ar[mt], aB + (uint32_t)(row * 128 + 16 * (((ks << 1) + aKf) ^ (row & 7))));
                }
                uint32_t br[4][2];
#pragma unroll
                for (int nt = 0; nt < 4; nt++) {
                    int row = wn + nt * 8 + tr;
                    ldsm_x2(br[nt], bB + (uint32_t)(row * 128 + 16 * (((ks << 1) + bKf) ^ (row & 7))));
                }
#pragma unroll
                for (int mt = 0; mt < 4; mt++)
#pragma unroll
                    for (int nt = 0; nt < 4; nt++)
                        mma_f16(acc2[mt][nt], ar[mt], br[nt]);
            }
        }
        __syncthreads();

        // phase 3: LN epilogue
        float* spart = (float*)(smem + SP_OFF);
        float* qpart = (float*)(smem + QP_OFF);
        float* muS   = (float*)(smem + MU_OFF);
        float* rsS   = (float*)(smem + RS_OFF);
        const int wni = wid >> 1;

#pragma unroll
        for (int mt = 0; mt < 4; mt++) {
            float sl = 0.f, ql = 0.f, sh = 0.f, qh = 0.f;
#pragma unroll
            for (int nt = 0; nt < 4; nt++) {
                int c0 = wn + nt * 8 + 2 * (lane & 3);
                float b0 = bias[c0], b1 = bias[c0 + 1];
                float z0 = acc2[mt][nt][0] + b0;
                float z1 = acc2[mt][nt][1] + b1;
                float z2 = acc2[mt][nt][2] + b0;
                float z3 = acc2[mt][nt][3] + b1;
                acc2[mt][nt][0] = z0; acc2[mt][nt][1] = z1;
                acc2[mt][nt][2] = z2; acc2[mt][nt][3] = z3;
                sl += z0 + z1; ql += z0 * z0 + z1 * z1;
                sh += z2 + z3; qh += z2 * z2 + z3 * z3;
            }
            sl += __shfl_xor_sync(0xffffffffu, sl, 1);
            sl += __shfl_xor_sync(0xffffffffu, sl, 2);
            ql += __shfl_xor_sync(0xffffffffu, ql, 1);
            ql += __shfl_xor_sync(0xffffffffu, ql, 2);
            sh += __shfl_xor_sync(0xffffffffu, sh, 1);
            sh += __shfl_xor_sync(0xffffffffu, sh, 2);
            qh += __shfl_xor_sync(0xffffffffu, qh, 1);
            qh += __shfl_xor_sync(0xffffffffu, qh, 2);
            if ((lane & 3) == 0) {
                int rlo = wm + mt * 16 + (lane >> 2);
                spart[rlo * 8 + wni] = sl;
                qpart[rlo * 8 + wni] = ql;
                spart[(rlo + 8) * 8 + wni] = sh;
                qpart[(rlo + 8) * 8 + wni] = qh;
            }
        }
        __syncthreads();
        if (tid < 128) {
            float s = 0.f, q = 0.f;
#pragma unroll
            for (int j = 0; j < 8; j++) { s += spart[tid * 8 + j]; q += qpart[tid * 8 + j]; }
            float mu  = s * (1.0f / HH);
            float var = q * (1.0f / HH) - mu * mu;
            muS[tid] = mu;
            rsS[tid] = rsqrtf(var + LN_EPS);
        }
        __syncthreads();

        __half* tile = (__half*)smem;
        const bool doT = (hTout != nullptr);
        float* hr = hres + ((size_t)b * NN + bm) * HH;
        float* df = dstF + ((size_t)b * NN + bm) * HH;

#pragma unroll
        for (int mt = 0; mt < 4; mt++) {
            int rl = wm + mt * 16 + (lane >> 2);
            int rh = rl + 8;
            float mul = muS[rl], rsl = rsS[rl];
            float muh = muS[rh], rsh = rsS[rh];
#pragma unroll
            for (int nt = 0; nt < 4; nt++) {
                int c0 = wn + nt * 8 + 2 * (lane & 3);
                float g0 = gamma[c0], g1 = gamma[c0 + 1];
                float e0 = beta[c0],  e1 = beta[c0 + 1];
                float y0 = fmaxf((acc2[mt][nt][0] - mul) * rsl * g0 + e0, 0.f) + hr[(long)rl * HH + c0];
                float y1 = fmaxf((acc2[mt][nt][1] - mul) * rsl * g1 + e1, 0.f) + hr[(long)rl * HH + c0 + 1];
                float y2 = fmaxf((acc2[mt][nt][2] - muh) * rsh * g0 + e0, 0.f) + hr[(long)rh * HH + c0];
                float y3 = fmaxf((acc2[mt][nt][3] - muh) * rsh * g1 + e1, 0.f) + hr[(long)rh * HH + c0 + 1];
                float2 vlo; vlo.x = y0; vlo.y = y1;
                float2 vhi; vhi.x = y2; vhi.y = y3;
                *(float2*)(df + (long)rl * HH + c0) = vlo;
                *(float2*)(df + (long)rh * HH + c0) = vhi;
                if (doT) {
                    tile[(c0)     * 136 + rl] = __float2half_rn(y0);
                    tile[(c0 + 1) * 136 + rl] = __float2half_rn(y1);
                    tile[(c0)     * 136 + rh] = __float2half_rn(y2);
                    tile[(c0 + 1) * 136 + rh] = __float2half_rn(y3);
                }
            }
        }

        if (doT) {
            __syncthreads();
            int c  = tid & 255;
            int hs = tid >> 8;
            __half* dst = hTout + (long)c * NN + bm + hs * 64;
            const uint4* src = (const uint4*)(tile + c * 136 + hs * 64);
#pragma unroll
            for (int g = 0; g < 8; g++)
                ((uint4*)dst)[g] = src[g];
        }

        // device-wide barrier before next layer reads hT (skip after last)
        if (!last) grid_barrier(l);
    }
}

// ---------------------------------------------------------------------------
// Launch orchestration (R9 schedule + persistent layers)
// ---------------------------------------------------------------------------
extern "C" void kernel_launch(void* const* d_in, const int* in_sizes, int n_in,
                              void* d_out, int out_size)
{
    const float* node_feat = (const float*)d_in[0];
    const float* edge_w    = (const float*)d_in[1];
    const float* adj       = (const float*)d_in[2];
    const float* W_in      = (const float*)d_in[3];
    const float* b_in      = (const float*)d_in[4];
    const float* g_in      = (const float*)d_in[5];
    const float* bt_in     = (const float*)d_in[6];
    const float* W         = (const float*)d_in[7];
    const float* bvec      = (const float*)d_in[8];
    const float* gamma     = (const float*)d_in[9];
    const float* beta      = (const float*)d_in[10];
    float* out = (float*)d_out;

    __half *na_p, *nf_p, *hTa_p, *hTb_p, *wT_p;
    float *h_p;
    cudaGetSymbolAddress((void**)&na_p,  g_norm_adj);
    cudaGetSymbolAddress((void**)&nf_p,  g_nf);
    cudaGetSymbolAddress((void**)&h_p,   g_h);
    cudaGetSymbolAddress((void**)&hTa_p, g_hTa);
    cudaGetSymbolAddress((void**)&hTb_p, g_hTb);
    cudaGetSymbolAddress((void**)&wT_p,  g_wT);

    cudaFuncSetAttribute(proj_fused,    cudaFuncAttributeMaxDynamicSharedMemorySize, FUSED_SMEM);
    cudaFuncSetAttribute(layers3_fused, cudaFuncAttributeMaxDynamicSharedMemorySize, FUSED_SMEM);

    // ONE side stream + 2 events (footprint proven safe in round 9)
    static cudaStream_t s_side = nullptr;
    static cudaEvent_t  s_fork = nullptr, s_join = nullptr;
    static bool s_init = false;
    if (!s_init) {
        s_init = true;
        if (cudaStreamCreateWithFlags(&s_side, cudaStreamNonBlocking) != cudaSuccess)
            s_side = nullptr;
        if (s_side) {
            if (cudaEventCreateWithFlags(&s_fork, cudaEventDisableTiming) != cudaSuccess ||
                cudaEventCreateWithFlags(&s_join, cudaEventDisableTiming) != cudaSuccess)
                s_side = nullptr;
        }
    }
    const bool multi = (s_side != nullptr);
    cudaStream_t side = multi ? s_side : (cudaStream_t)0;

    const int M_all = BB * NN;
    __half* winT = wT_p;
    __half* wlT  = wT_p + 256 * 512;

    if (multi) {
        cudaEventRecord(s_fork, 0);
        cudaStreamWaitEvent(side, s_fork, 0);
    }

    // main stream: normalized adjacency (DRAM-bound, ~56us)
    norm_adj_kernel<<<dim3(NN, BB), 256>>>(
        (const float4*)adj, (const float4*)edge_w, na_p);

    // side stream: weights + node_feat conversion + fused projection
    transpose_kernel<<<dim3(HH / 32, FF / 32, 1), dim3(32, 8), 0, side>>>(
        W_in, winT, FF, HH, 0, 0);
    transpose_kernel<<<dim3(HH / 32, HH / 32, LL), dim3(32, 8), 0, side>>>(
        W, wlT, HH, HH, (long)HH * HH, (long)HH * HH);
    half_copy_kernel<<<(int)(((long)M_all * FF / 4) / 256), 256, 0, side>>>(
        (const float4*)node_feat, (__half2*)nf_p);
    proj_fused<<<dim3(M_all / 128, 1), 512, FUSED_SMEM, side>>>(
        nf_p, winT, b_in, g_in, bt_in, h_p, hTa_p);

    if (multi) {
        cudaEventRecord(s_join, side);
        cudaStreamWaitEvent((cudaStream_t)0, s_join, 0);
    }

    // persistent 3-layer kernel (main stream): 128 co-resident CTAs
    layers3_fused<<<dim3(NN / 128, BB), 512, FUSED_SMEM>>>(
        na_p, hTa_p, hTb_p, wlT, bvec, gamma, beta, h_p, out);
}